// round 13
// baseline (speedup 1.0000x reference)
#include <cuda_runtime.h>
#include <cuda_fp16.h>
#include <cstdint>
#include <cstddef>

#define NBATCH 64
#define NTOT   8192
#define THRESH 0.02f
#define KT     64
#define MTILE  64
#define CPT    176                 // chunks per tile: 128 einsum + 48 stim
#define NTILE  128
#define TOTALW (NTILE * CPT)       // 22528 flat chunk-works
#define NCTA   296                 // 148 SMs x occ 2, single wave

// smem per buffer: Ahi 8K | Alo 8K | Bh 8K  (128B rows, SW128)
#define AHI_OFF 0
#define ALO_OFF 8192
#define BH_OFF  16384
#define BUFB    24576
#define SMEM_TOTAL (2 * BUFB)      // 49152 -> 2 CTAs/SM

__device__ float g_gatepart[16][4];
__device__ float g_accum[NBATCH * NTOT];
__device__ float g_outraw[NBATCH * 11];
__device__ int   g_tilecnt[NTILE];
__device__ int   g_done;

// ---------------- helpers ----------------
static __device__ __forceinline__ uint32_t smem_u32(const void* p) {
    uint32_t a;
    asm("{ .reg .u64 t; cvta.to.shared.u64 t, %1; cvt.u32.u64 %0, t; }" : "=r"(a) : "l"(p));
    return a;
}
#define SWZ(o) ((o) ^ (((o) >> 3) & 0x70))

static __device__ __forceinline__ void ldsm4(uint32_t* r, uint32_t addr) {
    asm volatile("ldmatrix.sync.aligned.m8n8.x4.shared.b16 {%0,%1,%2,%3}, [%4];"
                 : "=r"(r[0]), "=r"(r[1]), "=r"(r[2]), "=r"(r[3]) : "r"(addr));
}
static __device__ __forceinline__ void mma_f16(float* d, const uint32_t* a,
                                               uint32_t b0, uint32_t b1) {
    asm volatile("mma.sync.aligned.m16n8k16.row.col.f32.f16.f16.f32 "
                 "{%0,%1,%2,%3}, {%4,%5,%6,%7}, {%8,%9}, {%0,%1,%2,%3};"
                 : "+f"(d[0]), "+f"(d[1]), "+f"(d[2]), "+f"(d[3])
                 : "r"(a[0]), "r"(a[1]), "r"(a[2]), "r"(a[3]), "r"(b0), "r"(b1));
}
static __device__ __forceinline__ float gate_of(int i) {
    float s = 0.f;
#pragma unroll
    for (int sl = 0; sl < 16; sl++) s += g_gatepart[sl][i];
    return (s * (1.0f / 131072.0f) > THRESH) ? 1.f : 0.f;
}
static __device__ __forceinline__ int owner_of(int f) {
    return (int)(((long long)(f + 1) * NCTA - 1) / TOTALW);
}

// fp16 one-sided split: (a,b) -> hi pair + residual pair (lo half of reg = a)
static __device__ __forceinline__ void split2h(float a, float b, uint32_t& hp, uint32_t& lp) {
    asm("cvt.rn.f16x2.f32 %0, %1, %2;" : "=r"(hp) : "f"(b), "f"(a));
    __half2 h2 = *reinterpret_cast<__half2*>(&hp);
    float la = a - __low2float(h2);
    float lb = b - __high2float(h2);
    asm("cvt.rn.f16x2.f32 %0, %1, %2;" : "=r"(lp) : "f"(lb), "f"(la));
}
static __device__ __forceinline__ uint32_t pack2h(float a, float b) {
    uint32_t r;
    asm("cvt.rn.f16x2.f32 %0, %1, %2;" : "=r"(r) : "f"(b), "f"(a));
    return r;
}

// ---------------- init: zero scratch + gate partials ----------------
__global__ void init_kernel(const float* __restrict__ Z) {
    int blk = blockIdx.x, t = threadIdx.x;
    int idx = blk * 256 + t;
    float4* p = (float4*)g_accum;
#pragma unroll
    for (int j = 0; j < 4; j++) p[idx * 4 + j] = make_float4(0.f, 0.f, 0.f, 0.f);

    if (blk == 64) {
        for (int j = t; j < NBATCH * 11; j += 256) g_outraw[j] = 0.f;
        if (t < NTILE) g_tilecnt[t] = 0;
        if (t == 255) g_done = 0;
    }
    if (blk < 64) {
        int area = blk & 3, slice = blk >> 2;
        float s = 0.f;
#pragma unroll
        for (int it = 0; it < 8; it++) {
            int f = t + 256 * it;
            int b = slice * 4 + (f >> 9), a4 = f & 511;
            float4 v = *(const float4*)(Z + (size_t)b * NTOT + (size_t)area * 2048 + a4 * 4);
            s += fabsf(v.x) + fabsf(v.y) + fabsf(v.z) + fabsf(v.w);
        }
#pragma unroll
        for (int o = 16; o; o >>= 1) s += __shfl_xor_sync(0xffffffffu, s, o);
        __shared__ float ws[8];
        if ((t & 31) == 0) ws[t >> 5] = s;
        __syncthreads();
        if (t == 0) {
            float tot = 0.f;
            for (int w = 0; w < 8; w++) tot += ws[w];
            g_gatepart[slice][area] = tot;
        }
    }
}

// ---------------- main HMMA kernel: flat distribution + fused epilogue ----------------
__global__ __launch_bounds__(256, 2)
void main_kernel(const float* __restrict__ x, const float* __restrict__ Z,
                 const float* __restrict__ rw, const float* __restrict__ W,
                 const float* __restrict__ Mk,
                 const float* __restrict__ Fst, const float* __restrict__ rb,
                 const float* __restrict__ bias, const float* __restrict__ out_w,
                 const float* __restrict__ out_b, float* __restrict__ outp)
{
    extern __shared__ char smem[];
    __shared__ int s_last;
    const uint32_t sb = smem_u32(smem);
    const int t = threadIdx.x, wid = t >> 5, lid = t & 31;

    const int f0 = (int)((long long)blockIdx.x * TOTALW / NCTA);
    const int f1 = (int)((long long)(blockIdx.x + 1) * TOTALW / NCTA);

    float gates[4];
#pragma unroll
    for (int i = 0; i < 4; i++) gates[i] = gate_of(i);

    const int lr16 = t >> 4;
    const int lk = t & 15;

    float4 wv[4], mv[4], zv[4];
    uint2 ah2[4], al2[4], zh2[4];

    auto ldg = [&](int f) {
        int tile = f / CPT;
        int c = f - tile * CPT;
        int o = tile >> 5;
        int u0 = (tile & 31) * MTILE;
        if (c < 128) {
            int k0 = c * KT;
            int i = k0 >> 11, kl = k0 & 2047;
            const size_t base = ((size_t)(o * 4 + i) * 2048 + u0) * 2048 + kl + lk * 4;
#pragma unroll
            for (int v = 0; v < 4; v++) {
                size_t off = base + (size_t)(v * 16 + lr16) * 2048;
                wv[v] = *(const float4*)(W + off);
                mv[v] = *(const float4*)(Mk + off);
            }
#pragma unroll
            for (int v = 0; v < 4; v++)
                zv[v] = *(const float4*)(Z + (size_t)(v * 16 + lr16) * NTOT + k0 + lk * 4);
        } else {
            int k0 = (c - 128) * KT;
            int n0 = tile * MTILE;
#pragma unroll
            for (int v = 0; v < 4; v++)
                wv[v] = *(const float4*)(rw + (size_t)(n0 + v * 16 + lr16) * 3072 + k0 + lk * 4);
#pragma unroll
            for (int v = 0; v < 4; v++)
                zv[v] = *(const float4*)(x + (size_t)(v * 16 + lr16) * 3072 + k0 + lk * 4);
        }
    };

    auto chunk_is_einsum = [&](int f) { return (f % CPT) < 128; };
    auto chunk_gate = [&](int f) {
        int c = f % CPT;
        return (c < 128) ? gates[c >> 5] : 1.f;
    };

    auto cvtA = [&](int v, bool einsum) {
        float4 f = wv[v];
        if (einsum) {
            float4 m = mv[v];
            f.x *= __saturatef(m.x); f.y *= __saturatef(m.y);
            f.z *= __saturatef(m.z); f.w *= __saturatef(m.w);
        }
        split2h(f.x, f.y, ah2[v].x, al2[v].x);
        split2h(f.z, f.w, ah2[v].y, al2[v].y);
    };
    auto cvtZ = [&](int v, float zg) {
        float4 f = zv[v];
        zh2[v].x = pack2h(f.x * zg, f.y * zg);
        zh2[v].y = pack2h(f.z * zg, f.w * zg);
    };

    auto sts = [&](uint32_t buf) {
#pragma unroll
        for (int v = 0; v < 4; v++) {
            uint32_t sw = SWZ((uint32_t)((v * 16 + lr16) * 128 + lk * 8));
            asm volatile("st.shared.v2.b32 [%0], {%1,%2};" ::
                         "r"(buf + AHI_OFF + sw), "r"(ah2[v].x), "r"(ah2[v].y) : "memory");
            asm volatile("st.shared.v2.b32 [%0], {%1,%2};" ::
                         "r"(buf + ALO_OFF + sw), "r"(al2[v].x), "r"(al2[v].y) : "memory");
            asm volatile("st.shared.v2.b32 [%0], {%1,%2};" ::
                         "r"(buf + BH_OFF + sw), "r"(zh2[v].x), "r"(zh2[v].y) : "memory");
        }
    };

    const int mw = wid & 1, nw = wid >> 1;
    const int lr = lid & 15, lh = lid >> 4;
    const uint32_t a_row0 = (uint32_t)((mw * 32 + lr) * 128 + lh * 16);
    const uint32_t a_row1 = a_row0 + 16 * 128;
    const uint32_t b_row  = (uint32_t)((nw * 16 + lr) * 128 + lh * 16);

    float acc[4][4];
#pragma unroll
    for (int i = 0; i < 4; i++)
#pragma unroll
        for (int j = 0; j < 4; j++) acc[i][j] = 0.f;

    auto mma_kk = [&](uint32_t buf, int kk) {
        const uint32_t ko = (uint32_t)(kk * 32);
        uint32_t ah0[4], ah1[4], al0[4], al1[4], bh[4];
        ldsm4(ah0, buf + AHI_OFF + SWZ(a_row0 + ko));
        ldsm4(ah1, buf + AHI_OFF + SWZ(a_row1 + ko));
        ldsm4(bh,  buf + BH_OFF  + SWZ(b_row + ko));
        ldsm4(al0, buf + ALO_OFF + SWZ(a_row0 + ko));
        ldsm4(al1, buf + ALO_OFF + SWZ(a_row1 + ko));
        mma_f16(acc[0], ah0, bh[0], bh[2]);
        mma_f16(acc[1], ah0, bh[1], bh[3]);
        mma_f16(acc[2], ah1, bh[0], bh[2]);
        mma_f16(acc[3], ah1, bh[1], bh[3]);
        mma_f16(acc[0], al0, bh[0], bh[2]);
        mma_f16(acc[1], al0, bh[1], bh[3]);
        mma_f16(acc[2], al1, bh[0], bh[2]);
        mma_f16(acc[3], al1, bh[1], bh[3]);
    };

    const int r = lid >> 2, cp = (lid & 3) * 2;
    auto flush = [&](int tile) {
        int mbase = tile * MTILE + mw * 32;
#pragma unroll
        for (int mt = 0; mt < 2; mt++) {
#pragma unroll
            for (int nt = 0; nt < 2; nt++) {
                float* cc = acc[mt * 2 + nt];
                int m = mbase + mt * 16 + r;
                int nb = nw * 16 + nt * 8 + cp;
                atomicAdd(&g_accum[(size_t)nb * NTOT + m],           cc[0]);
                atomicAdd(&g_accum[(size_t)(nb + 1) * NTOT + m],     cc[1]);
                atomicAdd(&g_accum[(size_t)nb * NTOT + m + 8],       cc[2]);
                atomicAdd(&g_accum[(size_t)(nb + 1) * NTOT + m + 8], cc[3]);
                cc[0] = cc[1] = cc[2] = cc[3] = 0.f;
            }
        }
    };

    // fused epilogue for a completed tile: tanh + decay + output partials
    auto epilogue = [&](int tile) {
        const int n0t = tile * MTILE;
        const float g = gates[tile >> 5];
        const int b = t >> 2;                 // batch 0..63
        const int seg = (t & 3) * 16;         // 16 cols
        float zn[16];
#pragma unroll
        for (int q = 0; q < 4; q++) {
            int n = n0t + seg + q * 4;
            size_t gi = (size_t)b * NTOT + n;
            float4 a;
            a.x = __ldcg(&g_accum[gi]);     a.y = __ldcg(&g_accum[gi + 1]);
            a.z = __ldcg(&g_accum[gi + 2]); a.w = __ldcg(&g_accum[gi + 3]);
            float4 rv = *(const float4*)(rb + n);
            float4 bv = *(const float4*)(bias + n);
            float4 Fv = *(const float4*)(Fst + gi);
            float4 Zv = *(const float4*)(Z + gi);
            zn[q * 4 + 0] = tanhf(a.x + rv.x + bv.x * g - 0.8f * Fv.x - 0.4f * Zv.x);
            zn[q * 4 + 1] = tanhf(a.y + rv.y + bv.y * g - 0.8f * Fv.y - 0.4f * Zv.y);
            zn[q * 4 + 2] = tanhf(a.z + rv.z + bv.z * g - 0.8f * Fv.z - 0.4f * Zv.z);
            zn[q * 4 + 3] = tanhf(a.w + rv.w + bv.w * g - 0.8f * Fv.w - 0.4f * Zv.w);
        }
#pragma unroll
        for (int j = 0; j < 11; j++) {
            float p = 0.f;
#pragma unroll
            for (int q = 0; q < 4; q++) {
                float4 w = *(const float4*)(out_w + (size_t)j * NTOT + n0t + seg + q * 4);
                p += zn[q*4+0] * w.x + zn[q*4+1] * w.y + zn[q*4+2] * w.z + zn[q*4+3] * w.w;
            }
            p += __shfl_xor_sync(0xffffffffu, p, 1);
            p += __shfl_xor_sync(0xffffffffu, p, 2);
            if ((t & 3) == 0) atomicAdd(&g_outraw[b * 11 + j], p);
        }
    };

    // prologue
    ldg(f0);
    {
        bool e0 = chunk_is_einsum(f0);
        float zg0 = chunk_gate(f0);
#pragma unroll
        for (int v = 0; v < 4; v++) { cvtA(v, e0); cvtZ(v, zg0); }
        sts(sb);
    }
    __syncthreads();

    for (int f = f0; f < f1; f++) {
        const int p = (f - f0) & 1;
        const uint32_t buf = sb + (uint32_t)p * BUFB;
        const uint32_t nbuf = sb + (uint32_t)(p ^ 1) * BUFB;
        const bool have_next = (f + 1 < f1);
        bool ne = false; float nzg = 1.f;
        if (have_next) {
            ldg(f + 1);
            ne = chunk_is_einsum(f + 1);
            nzg = chunk_gate(f + 1);
        }
        mma_kk(buf, 0);
        mma_kk(buf, 1);
        mma_kk(buf, 2);
        if (have_next) { cvtA(0, ne); cvtA(1, ne); cvtZ(0, nzg); cvtZ(1, nzg); }
        mma_kk(buf, 3);
        if (have_next) {
            cvtA(2, ne); cvtA(3, ne); cvtZ(2, nzg); cvtZ(3, nzg);
            sts(nbuf);
        }
        __syncthreads();

        int tile = f / CPT;
        if (!have_next || ((f + 1) / CPT != tile)) {
            flush(tile);
            __threadfence();
            __syncthreads();
            if (t == 0) {
                int needed = owner_of((tile + 1) * CPT - 1) - owner_of(tile * CPT) + 1;
                int old = atomicAdd(&g_tilecnt[tile], 1);
                s_last = (old + 1 == needed) ? 1 : 0;
            }
            __syncthreads();
            if (s_last) {
                __threadfence();
                epilogue(tile);
                __threadfence();
                __syncthreads();
                if (t == 0) {
                    int od = atomicAdd(&g_done, 1);
                    s_last = (od + 1 == NTILE) ? 1 : 0;
                }
                __syncthreads();
                if (s_last) {
                    __threadfence();
                    for (int j = t; j < NBATCH * 11; j += 256) {
                        int jj = j % 11;
                        float rrr = __ldcg(&g_outraw[j]) + out_b[jj];
                        outp[j] = (jj < 10) ? rrr : 1.0f / (1.0f + expf(-rrr));
                    }
                }
            }
            __syncthreads();
        }
    }
}

// ---------------- launch ----------------
extern "C" void kernel_launch(void* const* d_in, const int* in_sizes, int n_in,
                              void* d_out, int out_size) {
    const float* x      = (const float*)d_in[0];
    const float* Z      = (const float*)d_in[1];
    const float* Fstate = (const float*)d_in[2];
    const float* rw     = (const float*)d_in[3];
    const float* rb     = (const float*)d_in[4];
    const float* W      = (const float*)d_in[5];
    const float* Mk     = (const float*)d_in[6];
    const float* bias_d = (const float*)d_in[7];
    const float* out_w  = (const float*)d_in[8];
    const float* out_b  = (const float*)d_in[9];
    float* out = (float*)d_out;

    cudaFuncSetAttribute(main_kernel, cudaFuncAttributeMaxDynamicSharedMemorySize, SMEM_TOTAL);

    init_kernel<<<128, 256>>>(Z);
    main_kernel<<<NCTA, 256, SMEM_TOTAL>>>(x, Z, rw, W, Mk,
                                           Fstate, rb, bias_d, out_w, out_b, out);
}

// round 14
// speedup vs baseline: 1.0363x; 1.0363x over previous
#include <cuda_runtime.h>
#include <cuda_fp16.h>
#include <cstdint>
#include <cstddef>

#define NBATCH 64
#define NTOT   8192
#define THRESH 0.02f
#define KT     64
#define MTILE  64
#define CPT    176                 // chunks per tile: 128 einsum + 48 stim
#define NTILE  128
#define TOTALW (NTILE * CPT)       // 22528 flat chunk-works
#define NCTA   296                 // 148 SMs x occ 2, single wave

// smem per buffer: Ahi 8K | Alo 8K | Bh 8K  (128B rows, SW128)
#define AHI_OFF 0
#define ALO_OFF 8192
#define BH_OFF  16384
#define BUFB    24576
#define SMEM_TOTAL (2 * BUFB)      // 49152 -> 2 CTAs/SM

__device__ float g_gatepart[16][4];
__device__ float g_accum[NBATCH * NTOT];
__device__ float g_outraw[NBATCH * 11];
__device__ int   g_tilecnt[NTILE];
__device__ int   g_done;

// ---------------- helpers ----------------
static __device__ __forceinline__ uint32_t smem_u32(const void* p) {
    uint32_t a;
    asm("{ .reg .u64 t; cvta.to.shared.u64 t, %1; cvt.u32.u64 %0, t; }" : "=r"(a) : "l"(p));
    return a;
}
#define SWZ(o) ((o) ^ (((o) >> 3) & 0x70))

static __device__ __forceinline__ void ldsm4(uint32_t* r, uint32_t addr) {
    asm volatile("ldmatrix.sync.aligned.m8n8.x4.shared.b16 {%0,%1,%2,%3}, [%4];"
                 : "=r"(r[0]), "=r"(r[1]), "=r"(r[2]), "=r"(r[3]) : "r"(addr));
}
static __device__ __forceinline__ void mma_f16(float* d, const uint32_t* a,
                                               uint32_t b0, uint32_t b1) {
    asm volatile("mma.sync.aligned.m16n8k16.row.col.f32.f16.f16.f32 "
                 "{%0,%1,%2,%3}, {%4,%5,%6,%7}, {%8,%9}, {%0,%1,%2,%3};"
                 : "+f"(d[0]), "+f"(d[1]), "+f"(d[2]), "+f"(d[3])
                 : "r"(a[0]), "r"(a[1]), "r"(a[2]), "r"(a[3]), "r"(b0), "r"(b1));
}
static __device__ __forceinline__ float gate_of(int i) {
    float s = 0.f;
#pragma unroll
    for (int sl = 0; sl < 16; sl++) s += g_gatepart[sl][i];
    return (s * (1.0f / 131072.0f) > THRESH) ? 1.f : 0.f;
}
static __device__ __forceinline__ int owner_of(int f) {
    return (int)(((long long)(f + 1) * NCTA - 1) / TOTALW);
}

// fp16 one-sided split: (a,b) -> hi pair + residual pair (lo half of reg = a)
static __device__ __forceinline__ void split2h(float a, float b, uint32_t& hp, uint32_t& lp) {
    asm("cvt.rn.f16x2.f32 %0, %1, %2;" : "=r"(hp) : "f"(b), "f"(a));
    __half2 h2 = *reinterpret_cast<__half2*>(&hp);
    float la = a - __low2float(h2);
    float lb = b - __high2float(h2);
    asm("cvt.rn.f16x2.f32 %0, %1, %2;" : "=r"(lp) : "f"(lb), "f"(la));
}
static __device__ __forceinline__ uint32_t pack2h(float a, float b) {
    uint32_t r;
    asm("cvt.rn.f16x2.f32 %0, %1, %2;" : "=r"(r) : "f"(b), "f"(a));
    return r;
}

// ---------------- init: zero scratch + gate partials ----------------
__global__ void init_kernel(const float* __restrict__ Z) {
    int blk = blockIdx.x, t = threadIdx.x;
    int idx = blk * 256 + t;
    float4* p = (float4*)g_accum;
#pragma unroll
    for (int j = 0; j < 4; j++) p[idx * 4 + j] = make_float4(0.f, 0.f, 0.f, 0.f);

    if (blk == 64) {
        for (int j = t; j < NBATCH * 11; j += 256) g_outraw[j] = 0.f;
        if (t < NTILE) g_tilecnt[t] = 0;
        if (t == 255) g_done = 0;
    }
    if (blk < 64) {
        int area = blk & 3, slice = blk >> 2;
        float s = 0.f;
#pragma unroll
        for (int it = 0; it < 8; it++) {
            int f = t + 256 * it;
            int b = slice * 4 + (f >> 9), a4 = f & 511;
            float4 v = *(const float4*)(Z + (size_t)b * NTOT + (size_t)area * 2048 + a4 * 4);
            s += fabsf(v.x) + fabsf(v.y) + fabsf(v.z) + fabsf(v.w);
        }
#pragma unroll
        for (int o = 16; o; o >>= 1) s += __shfl_xor_sync(0xffffffffu, s, o);
        __shared__ float ws[8];
        if ((t & 31) == 0) ws[t >> 5] = s;
        __syncthreads();
        if (t == 0) {
            float tot = 0.f;
            for (int w = 0; w < 8; w++) tot += ws[w];
            g_gatepart[slice][area] = tot;
        }
    }
}

// ---------------- main HMMA kernel: flat distribution + fused epilogue ----------------
__global__ __launch_bounds__(256, 2)
void main_kernel(const float* __restrict__ x, const float* __restrict__ Z,
                 const float* __restrict__ rw, const float* __restrict__ W,
                 const float* __restrict__ Mk,
                 const float* __restrict__ Fst, const float* __restrict__ rb,
                 const float* __restrict__ bias, const float* __restrict__ out_w,
                 const float* __restrict__ out_b, float* __restrict__ outp)
{
    extern __shared__ char smem[];
    __shared__ int s_last;
    const uint32_t sb = smem_u32(smem);
    const int t = threadIdx.x, wid = t >> 5, lid = t & 31;

    const int f0 = (int)((long long)blockIdx.x * TOTALW / NCTA);
    const int f1 = (int)((long long)(blockIdx.x + 1) * TOTALW / NCTA);

    float gates[4];
#pragma unroll
    for (int i = 0; i < 4; i++) gates[i] = gate_of(i);

    const int lr16 = t >> 4;
    const int lk = t & 15;

    float4 wv[4], mv[4], zv[4];
    uint2 ah2[4], al2[4], zh2[4];

    auto ldg = [&](int f) {
        int tile = f / CPT;
        int c = f - tile * CPT;
        int o = tile >> 5;
        int u0 = (tile & 31) * MTILE;
        if (c < 128) {
            int k0 = c * KT;
            int i = k0 >> 11, kl = k0 & 2047;
            const size_t base = ((size_t)(o * 4 + i) * 2048 + u0) * 2048 + kl + lk * 4;
#pragma unroll
            for (int v = 0; v < 4; v++) {
                size_t off = base + (size_t)(v * 16 + lr16) * 2048;
                wv[v] = *(const float4*)(W + off);
                mv[v] = *(const float4*)(Mk + off);
            }
#pragma unroll
            for (int v = 0; v < 4; v++)
                zv[v] = *(const float4*)(Z + (size_t)(v * 16 + lr16) * NTOT + k0 + lk * 4);
        } else {
            int k0 = (c - 128) * KT;
            int n0 = tile * MTILE;
#pragma unroll
            for (int v = 0; v < 4; v++)
                wv[v] = *(const float4*)(rw + (size_t)(n0 + v * 16 + lr16) * 3072 + k0 + lk * 4);
#pragma unroll
            for (int v = 0; v < 4; v++)
                zv[v] = *(const float4*)(x + (size_t)(v * 16 + lr16) * 3072 + k0 + lk * 4);
        }
    };

    auto chunk_is_einsum = [&](int f) { return (f % CPT) < 128; };
    auto chunk_gate = [&](int f) {
        int c = f % CPT;
        return (c < 128) ? gates[c >> 5] : 1.f;
    };

    auto cvtA = [&](int v, bool einsum) {
        float4 f = wv[v];
        if (einsum) {
            float4 m = mv[v];
            f.x *= __saturatef(m.x); f.y *= __saturatef(m.y);
            f.z *= __saturatef(m.z); f.w *= __saturatef(m.w);
        }
        split2h(f.x, f.y, ah2[v].x, al2[v].x);
        split2h(f.z, f.w, ah2[v].y, al2[v].y);
    };
    auto cvtZ = [&](int v, float zg) {
        float4 f = zv[v];
        zh2[v].x = pack2h(f.x * zg, f.y * zg);
        zh2[v].y = pack2h(f.z * zg, f.w * zg);
    };

    auto sts = [&](uint32_t buf) {
#pragma unroll
        for (int v = 0; v < 4; v++) {
            uint32_t sw = SWZ((uint32_t)((v * 16 + lr16) * 128 + lk * 8));
            asm volatile("st.shared.v2.b32 [%0], {%1,%2};" ::
                         "r"(buf + AHI_OFF + sw), "r"(ah2[v].x), "r"(ah2[v].y) : "memory");
            asm volatile("st.shared.v2.b32 [%0], {%1,%2};" ::
                         "r"(buf + ALO_OFF + sw), "r"(al2[v].x), "r"(al2[v].y) : "memory");
            asm volatile("st.shared.v2.b32 [%0], {%1,%2};" ::
                         "r"(buf + BH_OFF + sw), "r"(zh2[v].x), "r"(zh2[v].y) : "memory");
        }
    };

    // warp tile: mw in 0..3 (16 cols), nw in 0..1 (32 batches)
    const int mw = wid & 3, nw = wid >> 2;
    const int lr = lid & 15, lh = lid >> 4;
    const uint32_t a_row  = (uint32_t)((mw * 16 + lr) * 128 + lh * 16);
    const uint32_t b_row0 = (uint32_t)((nw * 32 + lr) * 128 + lh * 16);
    const uint32_t b_row1 = b_row0 + 16 * 128;

    float acc[4][4];
#pragma unroll
    for (int i = 0; i < 4; i++)
#pragma unroll
        for (int j = 0; j < 4; j++) acc[i][j] = 0.f;

    // 4 ldsm.x4 per kk (was 5): A dup x2 only via 16-col tiles, B dup x4 via 32-batch
    auto mma_kk = [&](uint32_t buf, int kk) {
        const uint32_t ko = (uint32_t)(kk * 32);
        uint32_t ah[4], al[4], bh0[4], bh1[4];
        ldsm4(bh0, buf + BH_OFF  + SWZ(b_row0 + ko));
        ldsm4(bh1, buf + BH_OFF  + SWZ(b_row1 + ko));
        ldsm4(ah,  buf + AHI_OFF + SWZ(a_row + ko));
        ldsm4(al,  buf + ALO_OFF + SWZ(a_row + ko));
        mma_f16(acc[0], ah, bh0[0], bh0[2]);
        mma_f16(acc[1], ah, bh0[1], bh0[3]);
        mma_f16(acc[2], ah, bh1[0], bh1[2]);
        mma_f16(acc[3], ah, bh1[1], bh1[3]);
        mma_f16(acc[0], al, bh0[0], bh0[2]);
        mma_f16(acc[1], al, bh0[1], bh0[3]);
        mma_f16(acc[2], al, bh1[0], bh1[2]);
        mma_f16(acc[3], al, bh1[1], bh1[3]);
    };

    const int r = lid >> 2, cp = (lid & 3) * 2;
    auto flush = [&](int tile) {
        int mbase = tile * MTILE + mw * 16;
        int m = mbase + r;
#pragma unroll
        for (int nt = 0; nt < 4; nt++) {
            float* cc = acc[nt];
            int nb = nw * 32 + nt * 8 + cp;
            atomicAdd(&g_accum[(size_t)nb * NTOT + m],           cc[0]);
            atomicAdd(&g_accum[(size_t)(nb + 1) * NTOT + m],     cc[1]);
            atomicAdd(&g_accum[(size_t)nb * NTOT + m + 8],       cc[2]);
            atomicAdd(&g_accum[(size_t)(nb + 1) * NTOT + m + 8], cc[3]);
            cc[0] = cc[1] = cc[2] = cc[3] = 0.f;
        }
    };

    // fused epilogue for a completed tile
    auto epilogue = [&](int tile) {
        const int n0t = tile * MTILE;
        const float g = gates[tile >> 5];
        const int b = t >> 2;
        const int seg = (t & 3) * 16;
        float zn[16];
#pragma unroll
        for (int q = 0; q < 4; q++) {
            int n = n0t + seg + q * 4;
            size_t gi = (size_t)b * NTOT + n;
            float4 a;
            a.x = __ldcg(&g_accum[gi]);     a.y = __ldcg(&g_accum[gi + 1]);
            a.z = __ldcg(&g_accum[gi + 2]); a.w = __ldcg(&g_accum[gi + 3]);
            float4 rv = *(const float4*)(rb + n);
            float4 bv = *(const float4*)(bias + n);
            float4 Fv = *(const float4*)(Fst + gi);
            float4 Zv = *(const float4*)(Z + gi);
            zn[q * 4 + 0] = tanhf(a.x + rv.x + bv.x * g - 0.8f * Fv.x - 0.4f * Zv.x);
            zn[q * 4 + 1] = tanhf(a.y + rv.y + bv.y * g - 0.8f * Fv.y - 0.4f * Zv.y);
            zn[q * 4 + 2] = tanhf(a.z + rv.z + bv.z * g - 0.8f * Fv.z - 0.4f * Zv.z);
            zn[q * 4 + 3] = tanhf(a.w + rv.w + bv.w * g - 0.8f * Fv.w - 0.4f * Zv.w);
        }
#pragma unroll
        for (int j = 0; j < 11; j++) {
            float p = 0.f;
#pragma unroll
            for (int q = 0; q < 4; q++) {
                float4 w = *(const float4*)(out_w + (size_t)j * NTOT + n0t + seg + q * 4);
                p += zn[q*4+0] * w.x + zn[q*4+1] * w.y + zn[q*4+2] * w.z + zn[q*4+3] * w.w;
            }
            p += __shfl_xor_sync(0xffffffffu, p, 1);
            p += __shfl_xor_sync(0xffffffffu, p, 2);
            if ((t & 3) == 0) atomicAdd(&g_outraw[b * 11 + j], p);
        }
    };

    // prologue
    ldg(f0);
    {
        bool e0 = chunk_is_einsum(f0);
        float zg0 = chunk_gate(f0);
#pragma unroll
        for (int v = 0; v < 4; v++) { cvtA(v, e0); cvtZ(v, zg0); }
        sts(sb);
    }
    __syncthreads();

    for (int f = f0; f < f1; f++) {
        const int p = (f - f0) & 1;
        const uint32_t buf = sb + (uint32_t)p * BUFB;
        const uint32_t nbuf = sb + (uint32_t)(p ^ 1) * BUFB;
        const bool have_next = (f + 1 < f1);
        bool ne = false; float nzg = 1.f;
        if (have_next) {
            ldg(f + 1);
            ne = chunk_is_einsum(f + 1);
            nzg = chunk_gate(f + 1);
        }
        mma_kk(buf, 0);
        mma_kk(buf, 1);
        mma_kk(buf, 2);
        if (have_next) { cvtA(0, ne); cvtA(1, ne); cvtZ(0, nzg); cvtZ(1, nzg); }
        mma_kk(buf, 3);
        if (have_next) {
            cvtA(2, ne); cvtA(3, ne); cvtZ(2, nzg); cvtZ(3, nzg);
            sts(nbuf);
        }
        __syncthreads();

        int tile = f / CPT;
        if (!have_next || ((f + 1) / CPT != tile)) {
            flush(tile);
            __threadfence();
            __syncthreads();
            if (t == 0) {
                int needed = owner_of((tile + 1) * CPT - 1) - owner_of(tile * CPT) + 1;
                int old = atomicAdd(&g_tilecnt[tile], 1);
                s_last = (old + 1 == needed) ? 1 : 0;
            }
            __syncthreads();
            if (s_last) {
                __threadfence();
                epilogue(tile);
                __threadfence();
                __syncthreads();
                if (t == 0) {
                    int od = atomicAdd(&g_done, 1);
                    s_last = (od + 1 == NTILE) ? 1 : 0;
                }
                __syncthreads();
                if (s_last) {
                    __threadfence();
                    for (int j = t; j < NBATCH * 11; j += 256) {
                        int jj = j % 11;
                        float rrr = __ldcg(&g_outraw[j]) + out_b[jj];
                        outp[j] = (jj < 10) ? rrr : 1.0f / (1.0f + expf(-rrr));
                    }
                }
            }
            __syncthreads();
        }
    }
}

// ---------------- launch ----------------
extern "C" void kernel_launch(void* const* d_in, const int* in_sizes, int n_in,
                              void* d_out, int out_size) {
    const float* x      = (const float*)d_in[0];
    const float* Z      = (const float*)d_in[1];
    const float* Fstate = (const float*)d_in[2];
    const float* rw     = (const float*)d_in[3];
    const float* rb     = (const float*)d_in[4];
    const float* W      = (const float*)d_in[5];
    const float* Mk     = (const float*)d_in[6];
    const float* bias_d = (const float*)d_in[7];
    const float* out_w  = (const float*)d_in[8];
    const float* out_b  = (const float*)d_in[9];
    float* out = (float*)d_out;

    cudaFuncSetAttribute(main_kernel, cudaFuncAttributeMaxDynamicSharedMemorySize, SMEM_TOTAL);

    init_kernel<<<128, 256>>>(Z);
    main_kernel<<<NCTA, 256, SMEM_TOTAL>>>(x, Z, rw, W, Mk,
                                           Fstate, rb, bias_d, out_w, out_b, out);
}